// round 9
// baseline (speedup 1.0000x reference)
#include <cuda_runtime.h>
#include <cuda_fp16.h>
#include <cuda_bf16.h>
#include <math.h>
#include <stdint.h>

#define F 256
#define N_MAX 65536
#define E_CAP (1 << 20)

// Scratch (allocation-free rule: __device__ globals)
__device__ int   g_cnt2[2 * N_MAX]; // [0,N): src counts, [N_MAX,2N): dst degree
__device__ int   g_off[N_MAX];      // CSR row offsets
__device__ int   g_cursor[N_MAX];   // fill cursors (init = off)
__device__ int   g_edst[E_CAP];     // CSR column (dst) indices
__device__ float g_dinv[N_MAX];
__device__ float g_X[(size_t)N_MAX * F];                 // fp32 init_res
__device__ __nv_bfloat16 g_Xb[(size_t)N_MAX * F];        // bf16 init_res (MMA A)
__device__ __nv_bfloat16 g_Wt[F * F];                    // bf16 (beta*W)^T, [n][k]
__device__ uint4 g_H16[(size_t)N_MAX * F / 8];           // fp16(H[j]*dinv[j])

// ---------------------------------------------------------------------------
// cp.async helpers
__device__ __forceinline__ uint32_t smem_u32(const void* p) {
    return (uint32_t)__cvta_generic_to_shared(p);
}
__device__ __forceinline__ void cp_async16(uint32_t dst, const void* src, int src_bytes) {
    asm volatile("cp.async.cg.shared.global [%0], [%1], 16, %2;\n"
                 :: "r"(dst), "l"(src), "r"(src_bytes));
}
__device__ __forceinline__ void cp_commit() {
    asm volatile("cp.async.commit_group;\n" ::);
}
template <int N>
__device__ __forceinline__ void cp_wait() {
    asm volatile("cp.async.wait_group %0;\n" :: "n"(N));
}

__device__ __forceinline__ float beta_from(const float* lamda_p, const void* l_p) {
    float lam = __ldg(lamda_p);
    int   li  = *reinterpret_cast<const int*>(l_p);
    float lf  = (li > 0 && li < (1 << 20)) ? (float)li
                                           : *reinterpret_cast<const float*>(l_p);
    return logf(lam / lf + 1.0f);
}

// ---------------------------------------------------------------------------
// histogram, 4 edges/thread via int4 (blocks [0, EB4)) +
// Wt = bf16((beta*W)^T) (blocks [EB4, EB4+16))
__global__ void k_count_weff(const int* __restrict__ ei, int E, int EB4,
                             const float* __restrict__ W,
                             const float* __restrict__ lamda_p,
                             const void* __restrict__ l_p) {
    if (blockIdx.x < EB4) {
        int q = blockIdx.x * blockDim.x + threadIdx.x;   // quad index
        int e4 = q * 4;
        if (e4 + 3 < E) {
            int4 s = reinterpret_cast<const int4*>(ei)[q];
            int4 d = reinterpret_cast<const int4*>(ei + E)[q];
            atomicAdd(&g_cnt2[s.x], 1); atomicAdd(&g_cnt2[s.y], 1);
            atomicAdd(&g_cnt2[s.z], 1); atomicAdd(&g_cnt2[s.w], 1);
            atomicAdd(&g_cnt2[N_MAX + d.x], 1); atomicAdd(&g_cnt2[N_MAX + d.y], 1);
            atomicAdd(&g_cnt2[N_MAX + d.z], 1); atomicAdd(&g_cnt2[N_MAX + d.w], 1);
        } else {
            for (int e = e4; e < E; e++) {
                atomicAdd(&g_cnt2[ei[e]], 1);
                atomicAdd(&g_cnt2[N_MAX + ei[E + e]], 1);
            }
        }
    } else {
        float beta = beta_from(lamda_p, l_p);
        int b = blockIdx.x - EB4;                 // 0..15
        int start = b * 4096;
        for (int t = threadIdx.x; t < 4096; t += 256) {
            int idx = start + t;                  // n*256 + k
            int nn = idx >> 8, kk = idx & 255;
            g_Wt[idx] = __float2bfloat16(beta * W[kk * F + nn]);
        }
    }
}

// ---------------------------------------------------------------------------
// single-block scan + node terms: g_off/g_cursor = exclusive scan of src
// counts; dinv = rsqrt(deg_in + 1). One block, 1024 threads, 2 global passes.
__global__ __launch_bounds__(1024)
void k_scan_node(int n) {
    const int tid  = threadIdx.x;
    const int lane = tid & 31;
    const int wid  = tid >> 5;
    const int PER  = (n + 1023) / 1024;
    const int base = tid * PER;

    // pass 1: per-thread chunk sum
    int s = 0;
    for (int j = 0; j < PER; j++) {
        int idx = base + j;
        if (idx < n) s += g_cnt2[idx];
    }
    // block scan of per-thread sums
    __shared__ int wsum[32];
    int x = s;
#pragma unroll
    for (int o = 1; o < 32; o <<= 1) {
        int y = __shfl_up_sync(0xffffffffu, x, o);
        if (lane >= o) x += y;
    }
    if (lane == 31) wsum[wid] = x;
    __syncthreads();
    if (wid == 0) {
        int w = wsum[lane];
        int xi = w;
#pragma unroll
        for (int o = 1; o < 32; o <<= 1) {
            int y = __shfl_up_sync(0xffffffffu, xi, o);
            if (lane >= o) xi += y;
        }
        wsum[lane] = xi - w;   // exclusive warp prefix
    }
    __syncthreads();
    int run = (x - s) + wsum[wid];   // exclusive prefix for this thread

    // pass 2: write offsets, cursors, dinv
    for (int j = 0; j < PER; j++) {
        int idx = base + j;
        if (idx < n) {
            int c = g_cnt2[idx];
            g_off[idx]    = run;
            g_cursor[idx] = run;
            run += c;
            float d = (float)g_cnt2[N_MAX + idx] + 1.0f;
            g_dinv[idx] = rsqrtf(d);
        }
    }
}

// ---------------------------------------------------------------------------
// fused: CSR fill, 4 edges/thread (blocks [0,EB4)) +
//        H16 = fp16(H * dinv) (blocks [EB4, EB4+HB))
__global__ void k_fill_h16(const int* __restrict__ ei, int E, int EB4,
                           const float* __restrict__ H, int n) {
    if (blockIdx.x < EB4) {
        int q = blockIdx.x * blockDim.x + threadIdx.x;
        int e4 = q * 4;
        if (e4 + 3 < E) {
            int4 s = reinterpret_cast<const int4*>(ei)[q];
            int4 d = reinterpret_cast<const int4*>(ei + E)[q];
            int p0 = atomicAdd(&g_cursor[s.x], 1);
            int p1 = atomicAdd(&g_cursor[s.y], 1);
            int p2 = atomicAdd(&g_cursor[s.z], 1);
            int p3 = atomicAdd(&g_cursor[s.w], 1);
            g_edst[p0] = d.x; g_edst[p1] = d.y;
            g_edst[p2] = d.z; g_edst[p3] = d.w;
        } else {
            for (int e = e4; e < E; e++) {
                int pos = atomicAdd(&g_cursor[ei[e]], 1);
                g_edst[pos] = ei[E + e];
            }
        }
    } else {
        int t = (blockIdx.x - EB4) * blockDim.x + threadIdx.x;  // one per 8 floats
        if (t < n * 32) {
            int node = t >> 5;
            float di = __ldg(&g_dinv[node]);
            const float4* Hp = reinterpret_cast<const float4*>(H) + (size_t)t * 2;
            float4 a = __ldg(Hp), b = __ldg(Hp + 1);
            __half2 p0 = __floats2half2_rn(a.x * di, a.y * di);
            __half2 p1 = __floats2half2_rn(a.z * di, a.w * di);
            __half2 p2 = __floats2half2_rn(b.x * di, b.y * di);
            __half2 p3 = __floats2half2_rn(b.z * di, b.w * di);
            uint4 o;
            o.x = *reinterpret_cast<uint32_t*>(&p0);
            o.y = *reinterpret_cast<uint32_t*>(&p1);
            o.z = *reinterpret_cast<uint32_t*>(&p2);
            o.w = *reinterpret_cast<uint32_t*>(&p3);
            g_H16[t] = o;
        }
    }
}

// ---------------------------------------------------------------------------
// fused aggregate + init: 1 warp per node, fp16 gather (8-edge unroll),
// fp32 accumulate. Self-loop folded via own H16 row (no fp32 H read).
// X[i] = (1-a)*dinv[i]*(sum_j H16[j] + H16[i]) + a*H0[i]
__device__ __forceinline__ void acc8(float* acc, uint4 v) {
    float2 f0 = __half22float2(*reinterpret_cast<__half2*>(&v.x));
    float2 f1 = __half22float2(*reinterpret_cast<__half2*>(&v.y));
    float2 f2 = __half22float2(*reinterpret_cast<__half2*>(&v.z));
    float2 f3 = __half22float2(*reinterpret_cast<__half2*>(&v.w));
    acc[0] += f0.x; acc[1] += f0.y;
    acc[2] += f1.x; acc[3] += f1.y;
    acc[4] += f2.x; acc[5] += f2.y;
    acc[6] += f3.x; acc[7] += f3.y;
}

__global__ __launch_bounds__(256)
void k_agg(const float* __restrict__ H0,
           const float* __restrict__ alpha_p, int n)
{
    int node = (blockIdx.x * blockDim.x + threadIdx.x) >> 5;
    if (node >= n) return;
    int lane = threadIdx.x & 31;

    const int base = g_off[node];
    const int cnt  = g_cnt2[node];

    float acc[8];
#pragma unroll
    for (int j = 0; j < 8; j++) acc[j] = 0.0f;

    // self loop: own pre-scaled row
    {
        uint4 vs = __ldg(&g_H16[(size_t)node * 32 + lane]);
        acc8(acc, vs);
    }

    int e = 0;
    for (; e + 8 <= cnt; e += 8) {
        int d[8];
#pragma unroll
        for (int j = 0; j < 8; j++) d[j] = __ldg(&g_edst[base + e + j]);
        uint4 v[8];
#pragma unroll
        for (int j = 0; j < 8; j++) v[j] = __ldg(&g_H16[(size_t)d[j] * 32 + lane]);
#pragma unroll
        for (int j = 0; j < 8; j++) acc8(acc, v[j]);
    }
    for (; e < cnt; e++) {
        int d0 = __ldg(&g_edst[base + e]);
        uint4 v0 = __ldg(&g_H16[(size_t)d0 * 32 + lane]);
        acc8(acc, v0);
    }

    float a   = __ldg(alpha_p);
    float oad = (1.0f - a) * g_dinv[node];
    size_t ro = (size_t)node * 64 + lane * 2;   // float4 index
    const float4* H04 = reinterpret_cast<const float4*>(H0);
    float4 z0 = __ldg(H04 + ro), z1 = __ldg(H04 + ro + 1);
    float4 r0, r1;
    r0.x = oad * acc[0] + a * z0.x;
    r0.y = oad * acc[1] + a * z0.y;
    r0.z = oad * acc[2] + a * z0.z;
    r0.w = oad * acc[3] + a * z0.w;
    r1.x = oad * acc[4] + a * z1.x;
    r1.y = oad * acc[5] + a * z1.y;
    r1.z = oad * acc[6] + a * z1.z;
    r1.w = oad * acc[7] + a * z1.w;
    float4* X4 = reinterpret_cast<float4*>(g_X);
    X4[ro]     = r0;
    X4[ro + 1] = r1;

    // bf16 copy for the MMA A operand
    __nv_bfloat162 b0 = __floats2bfloat162_rn(r0.x, r0.y);
    __nv_bfloat162 b1 = __floats2bfloat162_rn(r0.z, r0.w);
    __nv_bfloat162 b2 = __floats2bfloat162_rn(r1.x, r1.y);
    __nv_bfloat162 b3 = __floats2bfloat162_rn(r1.z, r1.w);
    uint4 ob;
    ob.x = *reinterpret_cast<uint32_t*>(&b0);
    ob.y = *reinterpret_cast<uint32_t*>(&b1);
    ob.z = *reinterpret_cast<uint32_t*>(&b2);
    ob.w = *reinterpret_cast<uint32_t*>(&b3);
    reinterpret_cast<uint4*>(g_Xb)[(size_t)node * 32 + lane] = ob;
}

// ---------------------------------------------------------------------------
// out = (1-beta)*X + Xb @ Wt^T   (bf16 m16n8k16 MMA; identity term fp32 in
// epilogue from g_X). Block 128x256, 512 threads = 16 warps (4M x 4N),
// warp tile 32x64, BK=32 (2 k16 steps), 2-stage cp.async.
#define AS_STRIDE 40                    // bf16 units; (20r+ln4) mod 32 bijective
#define BS_STRIDE 40
#define AS_ELEMS (128 * AS_STRIDE)
#define BS_ELEMS (256 * BS_STRIDE)
#define STAGE_ELEMS (AS_ELEMS + BS_ELEMS)
#define GEMM_SMEM_BYTES (2 * STAGE_ELEMS * 2)

__global__ __launch_bounds__(512, 1)
void k_gemm_bf16(float* __restrict__ out,
                 const float* __restrict__ lamda_p,
                 const void* __restrict__ l_p, int M)
{
    extern __shared__ __nv_bfloat16 smem[];
    __nv_bfloat16* As[2] = { smem, smem + STAGE_ELEMS };
    __nv_bfloat16* Bs[2] = { smem + AS_ELEMS, smem + STAGE_ELEMS + AS_ELEMS };

    const int tid   = threadIdx.x;
    const int warp  = tid >> 5;
    const int lane  = tid & 31;
    const int gid   = lane >> 2;
    const int ln4   = lane & 3;
    const int warpM = warp & 3;   // 0..3
    const int warpN = warp >> 2;  // 0..3
    const int blockRow = blockIdx.x * 128;

    float acc[2][8][4];
#pragma unroll
    for (int a = 0; a < 2; a++)
#pragma unroll
        for (int b = 0; b < 8; b++)
#pragma unroll
            for (int c = 0; c < 4; c++) acc[a][b][c] = 0.0f;

    auto prefetch = [&](int kt, int st) {
        int k0 = kt * 32;
        {   // A: 128 rows x 4 16B-chunks = 512 (1 per thread)
            int r = tid >> 2, c16 = tid & 3;
            int grow = blockRow + r;
            uint32_t dst = smem_u32(&As[st][r * AS_STRIDE + c16 * 8]);
            const void* src = &g_Xb[(size_t)(grow < M ? grow : 0) * F + k0 + c16 * 8];
            cp_async16(dst, src, grow < M ? 16 : 0);
        }
#pragma unroll
        for (int i = 0; i < 2; i++) {  // B: 256 n-rows x 4 chunks = 1024
            int idx = tid + i * 512;
            int r = idx >> 2, c16 = idx & 3;
            uint32_t dst = smem_u32(&Bs[st][r * BS_STRIDE + c16 * 8]);
            const void* src = &g_Wt[(size_t)r * F + k0 + c16 * 8];
            cp_async16(dst, src, 16);
        }
        cp_commit();
    };

    prefetch(0, 0);

#pragma unroll
    for (int kt = 0; kt < 8; kt++) {
        int st = kt & 1;
        if (kt + 1 < 8) {
            prefetch(kt + 1, st ^ 1);
            cp_wait<1>();
        } else {
            cp_wait<0>();
        }
        __syncthreads();

        const __nv_bfloat16* Ac = As[st];
        const __nv_bfloat16* Bc = Bs[st];
#pragma unroll
        for (int ks = 0; ks < 32; ks += 16) {
            uint32_t afr[2][4];
#pragma unroll
            for (int mt = 0; mt < 2; mt++) {
                int r0 = warpM * 32 + mt * 16 + gid;
                afr[mt][0] = *reinterpret_cast<const uint32_t*>(&Ac[r0 * AS_STRIDE + ks + 2 * ln4]);
                afr[mt][1] = *reinterpret_cast<const uint32_t*>(&Ac[(r0 + 8) * AS_STRIDE + ks + 2 * ln4]);
                afr[mt][2] = *reinterpret_cast<const uint32_t*>(&Ac[r0 * AS_STRIDE + ks + 8 + 2 * ln4]);
                afr[mt][3] = *reinterpret_cast<const uint32_t*>(&Ac[(r0 + 8) * AS_STRIDE + ks + 8 + 2 * ln4]);
            }
#pragma unroll
            for (int nt = 0; nt < 8; nt++) {
                int c0 = warpN * 64 + nt * 8 + gid;
                uint32_t b0 = *reinterpret_cast<const uint32_t*>(&Bc[c0 * BS_STRIDE + ks + 2 * ln4]);
                uint32_t b1 = *reinterpret_cast<const uint32_t*>(&Bc[c0 * BS_STRIDE + ks + 8 + 2 * ln4]);
#pragma unroll
                for (int mt = 0; mt < 2; mt++) {
                    asm volatile(
                        "mma.sync.aligned.m16n8k16.row.col.f32.bf16.bf16.f32 "
                        "{%0,%1,%2,%3}, {%4,%5,%6,%7}, {%8,%9}, {%0,%1,%2,%3};\n"
                        : "+f"(acc[mt][nt][0]), "+f"(acc[mt][nt][1]),
                          "+f"(acc[mt][nt][2]), "+f"(acc[mt][nt][3])
                        : "r"(afr[mt][0]), "r"(afr[mt][1]),
                          "r"(afr[mt][2]), "r"(afr[mt][3]),
                          "r"(b0), "r"(b1));
                }
            }
        }
        __syncthreads();
    }

    // epilogue: out = (1-beta)*X (fp32 from global) + acc
    const float obeta = 1.0f - beta_from(lamda_p, l_p);
#pragma unroll
    for (int mt = 0; mt < 2; mt++) {
#pragma unroll
        for (int half = 0; half < 2; half++) {
            int row = blockRow + warpM * 32 + mt * 16 + gid + half * 8;
            if (row >= M) continue;
#pragma unroll
            for (int nt = 0; nt < 8; nt++) {
                int col = warpN * 64 + nt * 8 + 2 * ln4;
                float2 xv = *reinterpret_cast<const float2*>(&g_X[(size_t)row * F + col]);
                float2 o;
                o.x = obeta * xv.x + acc[mt][nt][half * 2 + 0];
                o.y = obeta * xv.y + acc[mt][nt][half * 2 + 1];
                *reinterpret_cast<float2*>(&out[(size_t)row * F + col]) = o;
            }
        }
    }
}

// ---------------------------------------------------------------------------
extern "C" void kernel_launch(void* const* d_in, const int* in_sizes, int n_in,
                              void* d_out, int out_size) {
    const int*   ei    = (const int*)d_in[1];
    const float* H     = (const float*)d_in[0];
    const float* H0    = (const float*)d_in[2];
    const float* W     = (const float*)d_in[3];
    const float* lamda = (const float*)d_in[4];
    const float* alpha = (const float*)d_in[5];
    const void*  lp    = d_in[6];
    float* out = (float*)d_out;

    const int n = in_sizes[0] / F;   // 50000
    const int E = in_sizes[1] / 2;   // 800000
    const int EQ  = (E + 3) / 4;             // quads
    const int EB4 = (EQ + 255) / 256;        // edge blocks (4/thread)
    const int HB  = (n * 32 + 255) / 256;    // h16 conversion blocks

    // two memsets (also aligns ncu -s 5 onto k_agg)
    void* p_cnt2 = nullptr;
    cudaGetSymbolAddress(&p_cnt2, g_cnt2);
    cudaMemsetAsync(p_cnt2, 0, (size_t)N_MAX * sizeof(int), 0);
    cudaMemsetAsync((char*)p_cnt2 + (size_t)N_MAX * sizeof(int), 0,
                    (size_t)N_MAX * sizeof(int), 0);

    cudaFuncSetAttribute(k_gemm_bf16,
                         cudaFuncAttributeMaxDynamicSharedMemorySize,
                         GEMM_SMEM_BYTES);

    k_count_weff<<<EB4 + 16, 256>>>(ei, E, EB4, W, lamda, lp);
    k_scan_node<<<1, 1024>>>(n);
    k_fill_h16<<<EB4 + HB, 256>>>(ei, E, EB4, H, n);

    long long agg_threads = (long long)n * 32;   // 1 warp per node
    k_agg<<<(int)((agg_threads + 255) / 256), 256>>>(H0, alpha, n);

    k_gemm_bf16<<<(n + 127) / 128, 512, GEMM_SMEM_BYTES>>>(out, lamda, lp, n);
}

// round 11
// speedup vs baseline: 1.8135x; 1.8135x over previous
#include <cuda_runtime.h>
#include <cuda_fp16.h>
#include <cuda_bf16.h>
#include <math.h>
#include <stdint.h>

#define F 256
#define N_MAX 65536
#define E_CAP (1 << 20)
#define SCAN_CHUNK 2048

// Scratch (allocation-free rule: __device__ globals)
__device__ int   g_cnt2[2 * N_MAX]; // [0,N): src counts, [N_MAX,2N): dst degree
__device__ int   g_off[N_MAX];      // CSR row offsets
__device__ int   g_cursor[N_MAX];   // fill cursors (init = off)
__device__ int   g_partial[64];
__device__ int   g_edst[E_CAP];     // CSR column (dst) indices
__device__ float g_dinv[N_MAX];
__device__ float g_X[(size_t)N_MAX * F];                 // fp32 init_res
__device__ __nv_bfloat16 g_Xb[(size_t)N_MAX * F];        // bf16 init_res (MMA A)
__device__ __nv_bfloat16 g_Wt[F * F];                    // bf16 (beta*W)^T, [n][k]
__device__ uint4 g_H16[(size_t)N_MAX * F / 8];           // fp16(H[j]*dinv[j])

// ---------------------------------------------------------------------------
// cp.async helpers
__device__ __forceinline__ uint32_t smem_u32(const void* p) {
    return (uint32_t)__cvta_generic_to_shared(p);
}
__device__ __forceinline__ void cp_async16(uint32_t dst, const void* src, int src_bytes) {
    asm volatile("cp.async.cg.shared.global [%0], [%1], 16, %2;\n"
                 :: "r"(dst), "l"(src), "r"(src_bytes));
}
__device__ __forceinline__ void cp_commit() {
    asm volatile("cp.async.commit_group;\n" ::);
}
template <int N>
__device__ __forceinline__ void cp_wait() {
    asm volatile("cp.async.wait_group %0;\n" :: "n"(N));
}

__device__ __forceinline__ float beta_from(const float* lamda_p, const void* l_p) {
    float lam = __ldg(lamda_p);
    int   li  = *reinterpret_cast<const int*>(l_p);
    float lf  = (li > 0 && li < (1 << 20)) ? (float)li
                                           : *reinterpret_cast<const float*>(l_p);
    return logf(lam / lf + 1.0f);
}

// ---------------------------------------------------------------------------
// histogram (blocks [0, EB)) + Wt = bf16((beta*W)^T) (blocks [EB, EB+16))
__global__ void k_count_weff(const int* __restrict__ ei, int E, int EB,
                             const float* __restrict__ W,
                             const float* __restrict__ lamda_p,
                             const void* __restrict__ l_p) {
    if (blockIdx.x < EB) {
        int e = blockIdx.x * blockDim.x + threadIdx.x;
        if (e < E) {
            atomicAdd(&g_cnt2[ei[e]], 1);
            atomicAdd(&g_cnt2[N_MAX + ei[E + e]], 1);
        }
    } else {
        float beta = beta_from(lamda_p, l_p);
        int b = blockIdx.x - EB;                 // 0..15
        int start = b * 4096;
        for (int t = threadIdx.x; t < 4096; t += 256) {
            int idx = start + t;                 // n*256 + k
            int nn = idx >> 8, kk = idx & 255;
            g_Wt[idx] = __float2bfloat16(beta * W[kk * F + nn]);
        }
    }
}

// ---------------------------------------------------------------------------
// exclusive scan of src counts -> g_off (per-chunk), chunk totals to g_partial
__global__ void k_scan1(int n) {
    const int tid = threadIdx.x;
    const int base = blockIdx.x * SCAN_CHUNK;
    int v[8]; int s = 0;
#pragma unroll
    for (int j = 0; j < 8; j++) {
        int idx = base + tid * 8 + j;
        int c = (idx < n) ? g_cnt2[idx] : 0;
        v[j] = s; s += c;
    }
    __shared__ int sh[256];
    sh[tid] = s;
    __syncthreads();
    for (int o = 1; o < 256; o <<= 1) {
        int t = (tid >= o) ? sh[tid - o] : 0;
        __syncthreads();
        sh[tid] += t;
        __syncthreads();
    }
    int excl = sh[tid] - s;
#pragma unroll
    for (int j = 0; j < 8; j++) {
        int idx = base + tid * 8 + j;
        if (idx < n) g_off[idx] = excl + v[j];
    }
    if (tid == 255) g_partial[blockIdx.x] = sh[255];
}

// ---------------------------------------------------------------------------
// fused: partial-scan (redundant per block, nb<=32) + offsets + cursors + dinv
__global__ void k_scan3_node(int n) {
    __shared__ int s_add;
    int chunk = blockIdx.x >> 3;           // 2048 / 256
    if (threadIdx.x < 32) {
        int x = (threadIdx.x < chunk) ? g_partial[threadIdx.x] : 0;
#pragma unroll
        for (int o = 16; o > 0; o >>= 1) x += __shfl_xor_sync(0xffffffffu, x, o);
        if (threadIdx.x == 0) s_add = x;
    }
    __syncthreads();
    int i = blockIdx.x * blockDim.x + threadIdx.x;
    if (i < n) {
        int off = g_off[i] + s_add;
        g_off[i]    = off;
        g_cursor[i] = off;
        float d = (float)g_cnt2[N_MAX + i] + 1.0f;
        g_dinv[i] = rsqrtf(d);
    }
}

// ---------------------------------------------------------------------------
// fused: CSR fill (blocks [0,EB)) + H16 = fp16(H * dinv) (blocks [EB, EB+HB))
__global__ void k_fill_h16(const int* __restrict__ ei, int E, int EB,
                           const float* __restrict__ H, int n) {
    if (blockIdx.x < EB) {
        int e = blockIdx.x * blockDim.x + threadIdx.x;
        if (e < E) {
            int pos = atomicAdd(&g_cursor[ei[e]], 1);
            g_edst[pos] = ei[E + e];
        }
    } else {
        int t = (blockIdx.x - EB) * blockDim.x + threadIdx.x;  // one per 8 floats
        if (t < n * 32) {
            int node = t >> 5;
            float di = __ldg(&g_dinv[node]);
            const float4* Hp = reinterpret_cast<const float4*>(H) + (size_t)t * 2;
            float4 a = __ldg(Hp), b = __ldg(Hp + 1);
            __half2 p0 = __floats2half2_rn(a.x * di, a.y * di);
            __half2 p1 = __floats2half2_rn(a.z * di, a.w * di);
            __half2 p2 = __floats2half2_rn(b.x * di, b.y * di);
            __half2 p3 = __floats2half2_rn(b.z * di, b.w * di);
            uint4 o;
            o.x = *reinterpret_cast<uint32_t*>(&p0);
            o.y = *reinterpret_cast<uint32_t*>(&p1);
            o.z = *reinterpret_cast<uint32_t*>(&p2);
            o.w = *reinterpret_cast<uint32_t*>(&p3);
            g_H16[t] = o;
        }
    }
}

// ---------------------------------------------------------------------------
// fused aggregate + init: 1 warp per node, fp16 gather (8-edge unroll),
// fp32 accumulate. Self-loop folded via own H16 row (no fp32 H read).
// X[i] = (1-a)*dinv[i]*(sum_j H16[j] + H16[i]) + a*H0[i]
__device__ __forceinline__ void acc8(float* acc, uint4 v) {
    float2 f0 = __half22float2(*reinterpret_cast<__half2*>(&v.x));
    float2 f1 = __half22float2(*reinterpret_cast<__half2*>(&v.y));
    float2 f2 = __half22float2(*reinterpret_cast<__half2*>(&v.z));
    float2 f3 = __half22float2(*reinterpret_cast<__half2*>(&v.w));
    acc[0] += f0.x; acc[1] += f0.y;
    acc[2] += f1.x; acc[3] += f1.y;
    acc[4] += f2.x; acc[5] += f2.y;
    acc[6] += f3.x; acc[7] += f3.y;
}

__global__ __launch_bounds__(256)
void k_agg(const float* __restrict__ H0,
           const float* __restrict__ alpha_p, int n)
{
    int node = (blockIdx.x * blockDim.x + threadIdx.x) >> 5;
    if (node >= n) return;
    int lane = threadIdx.x & 31;

    const int base = g_off[node];
    const int cnt  = g_cnt2[node];

    float acc[8];
#pragma unroll
    for (int j = 0; j < 8; j++) acc[j] = 0.0f;

    // self loop: own pre-scaled row
    {
        uint4 vs = __ldg(&g_H16[(size_t)node * 32 + lane]);
        acc8(acc, vs);
    }

    int e = 0;
    for (; e + 8 <= cnt; e += 8) {
        int d[8];
#pragma unroll
        for (int j = 0; j < 8; j++) d[j] = __ldg(&g_edst[base + e + j]);
        uint4 v[8];
#pragma unroll
        for (int j = 0; j < 8; j++) v[j] = __ldg(&g_H16[(size_t)d[j] * 32 + lane]);
#pragma unroll
        for (int j = 0; j < 8; j++) acc8(acc, v[j]);
    }
    for (; e < cnt; e++) {
        int d0 = __ldg(&g_edst[base + e]);
        uint4 v0 = __ldg(&g_H16[(size_t)d0 * 32 + lane]);
        acc8(acc, v0);
    }

    float a   = __ldg(alpha_p);
    float oad = (1.0f - a) * g_dinv[node];
    size_t ro = (size_t)node * 64 + lane * 2;   // float4 index
    const float4* H04 = reinterpret_cast<const float4*>(H0);
    float4 z0 = __ldg(H04 + ro), z1 = __ldg(H04 + ro + 1);
    float4 r0, r1;
    r0.x = oad * acc[0] + a * z0.x;
    r0.y = oad * acc[1] + a * z0.y;
    r0.z = oad * acc[2] + a * z0.z;
    r0.w = oad * acc[3] + a * z0.w;
    r1.x = oad * acc[4] + a * z1.x;
    r1.y = oad * acc[5] + a * z1.y;
    r1.z = oad * acc[6] + a * z1.z;
    r1.w = oad * acc[7] + a * z1.w;
    float4* X4 = reinterpret_cast<float4*>(g_X);
    X4[ro]     = r0;
    X4[ro + 1] = r1;

    // bf16 copy for the MMA A operand
    __nv_bfloat162 b0 = __floats2bfloat162_rn(r0.x, r0.y);
    __nv_bfloat162 b1 = __floats2bfloat162_rn(r0.z, r0.w);
    __nv_bfloat162 b2 = __floats2bfloat162_rn(r1.x, r1.y);
    __nv_bfloat162 b3 = __floats2bfloat162_rn(r1.z, r1.w);
    uint4 ob;
    ob.x = *reinterpret_cast<uint32_t*>(&b0);
    ob.y = *reinterpret_cast<uint32_t*>(&b1);
    ob.z = *reinterpret_cast<uint32_t*>(&b2);
    ob.w = *reinterpret_cast<uint32_t*>(&b3);
    reinterpret_cast<uint4*>(g_Xb)[(size_t)node * 32 + lane] = ob;
}

// ---------------------------------------------------------------------------
// out = (1-beta)*X + Xb @ Wt^T   (bf16 m16n8k16 MMA; identity term fp32 in
// epilogue from g_X). Block 128x256, 512 threads = 16 warps (4M x 4N),
// warp tile 32x64, BK=32 (2 k16 steps), 2-stage cp.async.
#define AS_STRIDE 40                    // bf16 units; (20r+ln4) mod 32 bijective
#define BS_STRIDE 40
#define AS_ELEMS (128 * AS_STRIDE)
#define BS_ELEMS (256 * BS_STRIDE)
#define STAGE_ELEMS (AS_ELEMS + BS_ELEMS)
#define GEMM_SMEM_BYTES (2 * STAGE_ELEMS * 2)

__global__ __launch_bounds__(512, 1)
void k_gemm_bf16(float* __restrict__ out,
                 const float* __restrict__ lamda_p,
                 const void* __restrict__ l_p, int M)
{
    extern __shared__ __nv_bfloat16 smem[];
    __nv_bfloat16* As[2] = { smem, smem + STAGE_ELEMS };
    __nv_bfloat16* Bs[2] = { smem + AS_ELEMS, smem + STAGE_ELEMS + AS_ELEMS };

    const int tid   = threadIdx.x;
    const int warp  = tid >> 5;
    const int lane  = tid & 31;
    const int gid   = lane >> 2;
    const int ln4   = lane & 3;
    const int warpM = warp & 3;   // 0..3
    const int warpN = warp >> 2;  // 0..3
    const int blockRow = blockIdx.x * 128;

    float acc[2][8][4];
#pragma unroll
    for (int a = 0; a < 2; a++)
#pragma unroll
        for (int b = 0; b < 8; b++)
#pragma unroll
            for (int c = 0; c < 4; c++) acc[a][b][c] = 0.0f;

    auto prefetch = [&](int kt, int st) {
        int k0 = kt * 32;
        {   // A: 128 rows x 4 16B-chunks = 512 (1 per thread)
            int r = tid >> 2, c16 = tid & 3;
            int grow = blockRow + r;
            uint32_t dst = smem_u32(&As[st][r * AS_STRIDE + c16 * 8]);
            const void* src = &g_Xb[(size_t)(grow < M ? grow : 0) * F + k0 + c16 * 8];
            cp_async16(dst, src, grow < M ? 16 : 0);
        }
#pragma unroll
        for (int i = 0; i < 2; i++) {  // B: 256 n-rows x 4 chunks = 1024
            int idx = tid + i * 512;
            int r = idx >> 2, c16 = idx & 3;
            uint32_t dst = smem_u32(&Bs[st][r * BS_STRIDE + c16 * 8]);
            const void* src = &g_Wt[(size_t)r * F + k0 + c16 * 8];
            cp_async16(dst, src, 16);
        }
        cp_commit();
    };

    prefetch(0, 0);

#pragma unroll
    for (int kt = 0; kt < 8; kt++) {
        int st = kt & 1;
        if (kt + 1 < 8) {
            prefetch(kt + 1, st ^ 1);
            cp_wait<1>();
        } else {
            cp_wait<0>();
        }
        __syncthreads();

        const __nv_bfloat16* Ac = As[st];
        const __nv_bfloat16* Bc = Bs[st];
#pragma unroll
        for (int ks = 0; ks < 32; ks += 16) {
            uint32_t afr[2][4];
#pragma unroll
            for (int mt = 0; mt < 2; mt++) {
                int r0 = warpM * 32 + mt * 16 + gid;
                afr[mt][0] = *reinterpret_cast<const uint32_t*>(&Ac[r0 * AS_STRIDE + ks + 2 * ln4]);
                afr[mt][1] = *reinterpret_cast<const uint32_t*>(&Ac[(r0 + 8) * AS_STRIDE + ks + 2 * ln4]);
                afr[mt][2] = *reinterpret_cast<const uint32_t*>(&Ac[r0 * AS_STRIDE + ks + 8 + 2 * ln4]);
                afr[mt][3] = *reinterpret_cast<const uint32_t*>(&Ac[(r0 + 8) * AS_STRIDE + ks + 8 + 2 * ln4]);
            }
#pragma unroll
            for (int nt = 0; nt < 8; nt++) {
                int c0 = warpN * 64 + nt * 8 + gid;
                uint32_t b0 = *reinterpret_cast<const uint32_t*>(&Bc[c0 * BS_STRIDE + ks + 2 * ln4]);
                uint32_t b1 = *reinterpret_cast<const uint32_t*>(&Bc[c0 * BS_STRIDE + ks + 8 + 2 * ln4]);
#pragma unroll
                for (int mt = 0; mt < 2; mt++) {
                    asm volatile(
                        "mma.sync.aligned.m16n8k16.row.col.f32.bf16.bf16.f32 "
                        "{%0,%1,%2,%3}, {%4,%5,%6,%7}, {%8,%9}, {%0,%1,%2,%3};\n"
                        : "+f"(acc[mt][nt][0]), "+f"(acc[mt][nt][1]),
                          "+f"(acc[mt][nt][2]), "+f"(acc[mt][nt][3])
                        : "r"(afr[mt][0]), "r"(afr[mt][1]),
                          "r"(afr[mt][2]), "r"(afr[mt][3]),
                          "r"(b0), "r"(b1));
                }
            }
        }
        __syncthreads();
    }

    // epilogue: out = (1-beta)*X (fp32 from global) + acc
    const float obeta = 1.0f - beta_from(lamda_p, l_p);
#pragma unroll
    for (int mt = 0; mt < 2; mt++) {
#pragma unroll
        for (int half = 0; half < 2; half++) {
            int row = blockRow + warpM * 32 + mt * 16 + gid + half * 8;
            if (row >= M) continue;
#pragma unroll
            for (int nt = 0; nt < 8; nt++) {
                int col = warpN * 64 + nt * 8 + 2 * ln4;
                float2 xv = *reinterpret_cast<const float2*>(&g_X[(size_t)row * F + col]);
                float2 o;
                o.x = obeta * xv.x + acc[mt][nt][half * 2 + 0];
                o.y = obeta * xv.y + acc[mt][nt][half * 2 + 1];
                *reinterpret_cast<float2*>(&out[(size_t)row * F + col]) = o;
            }
        }
    }
}

// ---------------------------------------------------------------------------
extern "C" void kernel_launch(void* const* d_in, const int* in_sizes, int n_in,
                              void* d_out, int out_size) {
    const float* H     = (const float*)d_in[0];
    const int*   ei    = (const int*)d_in[1];
    const float* H0    = (const float*)d_in[2];
    const float* W     = (const float*)d_in[3];
    const float* lamda = (const float*)d_in[4];
    const float* alpha = (const float*)d_in[5];
    const void*  lp    = d_in[6];
    float* out = (float*)d_out;

    const int n = in_sizes[0] / F;   // 50000
    const int E = in_sizes[1] / 2;   // 800000
    const int nScanBlocks = (n + SCAN_CHUNK - 1) / SCAN_CHUNK;
    const int EB = (E + 255) / 256;
    const int HB = (n * 32 + 255) / 256;

    // two memsets (aligns ncu -s 5 onto k_agg)
    void* p_cnt2 = nullptr;
    cudaGetSymbolAddress(&p_cnt2, g_cnt2);
    cudaMemsetAsync(p_cnt2, 0, (size_t)N_MAX * sizeof(int), 0);
    cudaMemsetAsync((char*)p_cnt2 + (size_t)N_MAX * sizeof(int), 0,
                    (size_t)N_MAX * sizeof(int), 0);

    cudaFuncSetAttribute(k_gemm_bf16,
                         cudaFuncAttributeMaxDynamicSharedMemorySize,
                         GEMM_SMEM_BYTES);

    k_count_weff<<<EB + 16, 256>>>(ei, E, EB, W, lamda, lp);
    k_scan1<<<nScanBlocks, 256>>>(n);
    k_scan3_node<<<(n + 255) / 256, 256>>>(n);
    k_fill_h16<<<EB + HB, 256>>>(ei, E, EB, H, n);

    long long agg_threads = (long long)n * 32;   // 1 warp per node
    k_agg<<<(int)((agg_threads + 255) / 256), 256>>>(H0, alpha, n);

    k_gemm_bf16<<<(n + 127) / 128, 512, GEMM_SMEM_BYTES>>>(out, lamda, lp, n);
}